// round 1
// baseline (speedup 1.0000x reference)
#include <cuda_runtime.h>
#include <cuda_bf16.h>

#define BDIM 128
#define TILE 1024
#define NPTS 8192
#define NB   4

// Scratch for per-point min distances (allocation-free: device globals).
__device__ float g_dist[2][NB * NPTS];

// One block = 128 consecutive "A" points of one batch, one direction.
// Loops over all M "B" points via shared-memory tiles pre-transformed to
// (-2x, -2y, -2z, ||b||^2) so the inner loop is 1 LDS.128 + FADD + 3 FFMA + FMNMX.
__global__ __launch_bounds__(BDIM) void min_dist_kernel(
    const float* __restrict__ xyz1,
    const float* __restrict__ xyz2)
{
    __shared__ float4 sB[TILE];

    const int dir = blockIdx.z;                 // 0: A=xyz1,B=xyz2 ; 1: swapped
    const float* Aall = (dir == 0) ? xyz1 : xyz2;
    const float* Ball = (dir == 0) ? xyz2 : xyz1;

    const int b = blockIdx.y;
    const float* Abase = Aall + (size_t)b * NPTS * 3;
    const float* Bbase = Ball + (size_t)b * NPTS * 3;

    const int aIdx = blockIdx.x * BDIM + threadIdx.x;
    const float ax = Abase[aIdx * 3 + 0];
    const float ay = Abase[aIdx * 3 + 1];
    const float az = Abase[aIdx * 3 + 2];
    const float s1 = ax * ax + ay * ay + az * az;

    float best = 3.402823e38f;

    for (int t0 = 0; t0 < NPTS; t0 += TILE) {
        __syncthreads();
        // Cooperative tile load + transform.
        for (int i = threadIdx.x; i < TILE; i += BDIM) {
            const float* p = Bbase + (size_t)(t0 + i) * 3;
            float x = p[0], y = p[1], z = p[2];
            sB[i] = make_float4(-2.0f * x, -2.0f * y, -2.0f * z,
                                x * x + y * y + z * z);
        }
        __syncthreads();

        #pragma unroll 8
        for (int i = 0; i < TILE; i++) {
            float4 q = sB[i];
            float d = s1 + q.w;
            d = fmaf(q.x, ax, d);
            d = fmaf(q.y, ay, d);
            d = fmaf(q.z, az, d);
            best = fminf(best, d);
        }
    }

    g_dist[dir][b * NPTS + aIdx] = fmaxf(best, 0.0f);
}

// Single-block deterministic weighted-mean reduction over both directions.
__global__ __launch_bounds__(1024) void reduce_kernel(
    const float* __restrict__ w1,
    const float* __restrict__ w2,
    float* __restrict__ out)
{
    __shared__ float s[4][32];

    float n1 = 0.f, d1 = 0.f, n2 = 0.f, d2 = 0.f;
    for (int i = threadIdx.x; i < NB * NPTS; i += 1024) {
        float a  = g_dist[0][i];
        float wa = w1[i];
        n1 = fmaf(a, wa, n1);
        d1 += wa;
        float bb = g_dist[1][i];
        float wb = w2[i];
        n2 = fmaf(bb, wb, n2);
        d2 += wb;
    }

    #pragma unroll
    for (int off = 16; off > 0; off >>= 1) {
        n1 += __shfl_down_sync(0xffffffffu, n1, off);
        d1 += __shfl_down_sync(0xffffffffu, d1, off);
        n2 += __shfl_down_sync(0xffffffffu, n2, off);
        d2 += __shfl_down_sync(0xffffffffu, d2, off);
    }

    const int wid = threadIdx.x >> 5;
    const int lid = threadIdx.x & 31;
    if (lid == 0) {
        s[0][wid] = n1; s[1][wid] = d1; s[2][wid] = n2; s[3][wid] = d2;
    }
    __syncthreads();

    if (threadIdx.x == 0) {
        float N1 = 0.f, D1 = 0.f, N2 = 0.f, D2 = 0.f;
        #pragma unroll
        for (int w = 0; w < 32; w++) {
            N1 += s[0][w]; D1 += s[1][w]; N2 += s[2][w]; D2 += s[3][w];
        }
        out[0] = 0.5f * (N1 / D1 + N2 / D2);
    }
}

extern "C" void kernel_launch(void* const* d_in, const int* in_sizes, int n_in,
                              void* d_out, int out_size)
{
    const float* xyz1 = (const float*)d_in[0];
    const float* xyz2 = (const float*)d_in[1];
    const float* w1   = (const float*)d_in[2];
    const float* w2   = (const float*)d_in[3];
    float* out        = (float*)d_out;

    dim3 grid(NPTS / BDIM, NB, 2);   // 64 x 4 x 2 = 512 blocks
    min_dist_kernel<<<grid, BDIM>>>(xyz1, xyz2);
    reduce_kernel<<<1, 1024>>>(w1, w2, out);
}

// round 2
// speedup vs baseline: 1.1279x; 1.1279x over previous
#include <cuda_runtime.h>
#include <cuda_bf16.h>

#define BDIM 128
#define TILE 1024          // B points per smem tile
#define NPAIR (TILE / 2)
#define NPTS 8192
#define NB   4
#define BLKS_PER_DIR (NB * (NPTS / BDIM))   // 256

// Per-block partial sums: [dir][block] -> (sum w*d, sum w)
__device__ float g_pnum[2][BLKS_PER_DIR];
__device__ float g_pden[2][BLKS_PER_DIR];

#define PACK2(dst, lo, hi) \
    asm("mov.b64 %0, {%1, %2};" : "=l"(dst) : "r"(__float_as_uint(lo)), "r"(__float_as_uint(hi)))
#define UNPACK2(lo, hi, src) \
    { unsigned _ulo, _uhi; \
      asm("mov.b64 {%0, %1}, %2;" : "=r"(_ulo), "=r"(_uhi) : "l"(src)); \
      lo = __uint_as_float(_ulo); hi = __uint_as_float(_uhi); }
#define ADD2(d, a, b) \
    asm("add.rn.f32x2 %0, %1, %2;" : "=l"(d) : "l"(a), "l"(b))
#define FMA2(d, a, b, c) \
    asm("fma.rn.f32x2 %0, %1, %2, %3;" : "=l"(d) : "l"(a), "l"(b), "l"(c))

// One block = 128 consecutive "A" points of one batch, one direction.
// smem tile holds B points pairwise-SoA: sXY[j]=(x0,x1,y0,y1), sZW[j]=(z0,z1,w0,w1)
// where the B coords are pre-transformed to (-2x,-2y,-2z,||b||^2).
// Inner loop per 2 B points: 2x LDS.128 + add.f32x2 + 3x fma.f32x2 + 2x FMNMX.
__global__ __launch_bounds__(BDIM) void min_dist_kernel(
    const float* __restrict__ xyz1,
    const float* __restrict__ xyz2,
    const float* __restrict__ w1,
    const float* __restrict__ w2)
{
    __shared__ float4 sXY[NPAIR];
    __shared__ float4 sZW[NPAIR];
    __shared__ float sred[8];

    const int dir = blockIdx.z;
    const float* Aall = (dir == 0) ? xyz1 : xyz2;
    const float* Ball = (dir == 0) ? xyz2 : xyz1;
    const float* Wall = (dir == 0) ? w1   : w2;

    const int b = blockIdx.y;
    const float* Abase = Aall + (size_t)b * NPTS * 3;
    const float* Bbase = Ball + (size_t)b * NPTS * 3;

    const int aIdx = blockIdx.x * BDIM + threadIdx.x;
    const float ax = Abase[aIdx * 3 + 0];
    const float ay = Abase[aIdx * 3 + 1];
    const float az = Abase[aIdx * 3 + 2];
    const float s1 = ax * ax + ay * ay + az * az;

    unsigned long long axax, ayay, azaz, s1s1;
    PACK2(axax, ax, ax);
    PACK2(ayay, ay, ay);
    PACK2(azaz, az, az);
    PACK2(s1s1, s1, s1);

    float best0 = 3.402823e38f;
    float best1 = 3.402823e38f;

    for (int t0 = 0; t0 < NPTS; t0 += TILE) {
        __syncthreads();
        for (int j = threadIdx.x; j < NPAIR; j += BDIM) {
            const float* p0 = Bbase + (size_t)(t0 + 2 * j) * 3;
            float x0 = p0[0], y0 = p0[1], z0 = p0[2];
            float x1 = p0[3], y1 = p0[4], z1 = p0[5];
            sXY[j] = make_float4(-2.0f * x0, -2.0f * x1, -2.0f * y0, -2.0f * y1);
            sZW[j] = make_float4(-2.0f * z0, -2.0f * z1,
                                 x0 * x0 + y0 * y0 + z0 * z0,
                                 x1 * x1 + y1 * y1 + z1 * z1);
        }
        __syncthreads();

        #pragma unroll 8
        for (int j = 0; j < NPAIR; j++) {
            float4 xy = sXY[j];
            float4 zw = sZW[j];
            unsigned long long x01, y01, z01, w01, d;
            PACK2(x01, xy.x, xy.y);
            PACK2(y01, xy.z, xy.w);
            PACK2(z01, zw.x, zw.y);
            PACK2(w01, zw.z, zw.w);
            ADD2(d, s1s1, w01);
            FMA2(d, x01, axax, d);
            FMA2(d, y01, ayay, d);
            FMA2(d, z01, azaz, d);
            float d0, d1;
            UNPACK2(d0, d1, d);
            best0 = fminf(best0, d0);
            best1 = fminf(best1, d1);
        }
    }

    const float w = Wall[b * NPTS + aIdx];
    float num = fmaxf(fminf(best0, best1), 0.0f) * w;
    float den = w;

    // Fixed-order block reduction (deterministic).
    #pragma unroll
    for (int off = 16; off > 0; off >>= 1) {
        num += __shfl_down_sync(0xffffffffu, num, off);
        den += __shfl_down_sync(0xffffffffu, den, off);
    }
    const int wid = threadIdx.x >> 5;
    if ((threadIdx.x & 31) == 0) {
        sred[wid] = num;
        sred[4 + wid] = den;
    }
    __syncthreads();
    if (threadIdx.x == 0) {
        float n = sred[0] + sred[1] + sred[2] + sred[3];
        float dd = sred[4] + sred[5] + sred[6] + sred[7];
        const int blk = b * (NPTS / BDIM) + blockIdx.x;
        g_pnum[dir][blk] = n;
        g_pden[dir][blk] = dd;
    }
}

// Combine 256 partials per direction. Single block, fixed order.
__global__ __launch_bounds__(256) void combine_kernel(float* __restrict__ out)
{
    __shared__ float s[4][8];
    const int t = threadIdx.x;

    float n1 = g_pnum[0][t];
    float d1 = g_pden[0][t];
    float n2 = g_pnum[1][t];
    float d2 = g_pden[1][t];

    #pragma unroll
    for (int off = 16; off > 0; off >>= 1) {
        n1 += __shfl_down_sync(0xffffffffu, n1, off);
        d1 += __shfl_down_sync(0xffffffffu, d1, off);
        n2 += __shfl_down_sync(0xffffffffu, n2, off);
        d2 += __shfl_down_sync(0xffffffffu, d2, off);
    }
    const int wid = t >> 5;
    if ((t & 31) == 0) {
        s[0][wid] = n1; s[1][wid] = d1; s[2][wid] = n2; s[3][wid] = d2;
    }
    __syncthreads();
    if (t == 0) {
        float N1 = 0.f, D1 = 0.f, N2 = 0.f, D2 = 0.f;
        #pragma unroll
        for (int w = 0; w < 8; w++) {
            N1 += s[0][w]; D1 += s[1][w]; N2 += s[2][w]; D2 += s[3][w];
        }
        out[0] = 0.5f * (N1 / D1 + N2 / D2);
    }
}

extern "C" void kernel_launch(void* const* d_in, const int* in_sizes, int n_in,
                              void* d_out, int out_size)
{
    const float* xyz1 = (const float*)d_in[0];
    const float* xyz2 = (const float*)d_in[1];
    const float* w1   = (const float*)d_in[2];
    const float* w2   = (const float*)d_in[3];
    float* out        = (float*)d_out;

    dim3 grid(NPTS / BDIM, NB, 2);   // 64 x 4 x 2 = 512 blocks
    min_dist_kernel<<<grid, BDIM>>>(xyz1, xyz2, w1, w2);
    combine_kernel<<<1, 256>>>(out);
}

// round 3
// speedup vs baseline: 2.1018x; 1.8635x over previous
#include <cuda_runtime.h>
#include <cuda_bf16.h>

#define NPTS 8192
#define NB 4
#define NPAIRS (NPTS / 2)              // 4096 pairs per (array,batch)
#define BDIM 64
#define TA 4                           // A points per lane
#define A_PER_BLK (BDIM * TA)          // 256
#define NACHUNK (NPTS / A_PER_BLK)     // 32
#define NBCHUNK 8
#define BCHUNK_PTS (NPTS / NBCHUNK)    // 1024 B points per chunk
#define TILE_PAIRS 256                 // 256 pairs = 512 B points = 8KB smem
#define TILES_PER_CHUNK (BCHUNK_PTS / (2 * TILE_PAIRS))  // 2
#define NBLOCKS (2 * NB * NACHUNK * NBCHUNK)             // 2048

// Transformed B point-pairs: [arr][b][pair][4] = {x01, y01, z01, w01}
// where x01 packs (-2*x0, -2*x1), w01 packs (||b0||^2, ||b1||^2).
__device__ unsigned long long g_bt[2][NB][NPAIRS][4];
// Per-A-point running min of d' = d - s1, as order-mapped uint for atomicMin.
__device__ unsigned g_slot[2][NB][NPTS];
// Partial weighted sums from combine1: [block][n0,d0,n1,d1]
__device__ float g_part[64][4];

#define PACK2(dst, lo, hi) \
    asm("mov.b64 %0, {%1, %2};" : "=l"(dst) : "r"(__float_as_uint(lo)), "r"(__float_as_uint(hi)))
#define UNPACK2(lo, hi, src) \
    { unsigned _ulo, _uhi; \
      asm("mov.b64 {%0, %1}, %2;" : "=r"(_ulo), "=r"(_uhi) : "l"(src)); \
      lo = __uint_as_float(_ulo); hi = __uint_as_float(_uhi); }
#define FMA2(d, a, b, c) \
    asm("fma.rn.f32x2 %0, %1, %2, %3;" : "=l"(d) : "l"(a), "l"(b), "l"(c))
#define LDS_V2U64(r0, r1, addr) \
    asm volatile("ld.shared.v2.u64 {%0, %1}, [%2];" : "=l"(r0), "=l"(r1) : "r"(addr))

__device__ __forceinline__ unsigned f2key(float f) {
    unsigned u = __float_as_uint(f);
    unsigned m = (unsigned)((int)u >> 31);
    return u ^ (m | 0x80000000u);
}
__device__ __forceinline__ float key2f(unsigned key) {
    unsigned m = (unsigned)((int)key >> 31);   // all-ones if top bit set
    return __uint_as_float(key ^ ((~m) | 0x80000000u));
}

// k1: transform both point clouds into pair-SoA + init min slots.
__global__ __launch_bounds__(256) void transform_kernel(
    const float* __restrict__ xyz1,
    const float* __restrict__ xyz2)
{
    const int t = blockIdx.x * 256 + threadIdx.x;     // 0..32767
    // init 2 min slots each (65536 slots total)
    ((unsigned*)g_slot)[t] = 0xFFFFFFFFu;
    ((unsigned*)g_slot)[t + 32768] = 0xFFFFFFFFu;

    const int arr = t >> 14;
    const int rem = t & 16383;
    const int b = rem >> 12;
    const int j = rem & 4095;
    const float* src = (arr ? xyz2 : xyz1) + (size_t)(b * NPTS + 2 * j) * 3;
    float x0 = src[0], y0 = src[1], z0 = src[2];
    float x1 = src[3], y1 = src[4], z1 = src[5];

    unsigned long long X, Y, Z, W;
    PACK2(X, -2.0f * x0, -2.0f * x1);
    PACK2(Y, -2.0f * y0, -2.0f * y1);
    PACK2(Z, -2.0f * z0, -2.0f * z1);
    PACK2(W, x0 * x0 + y0 * y0 + z0 * z0, x1 * x1 + y1 * y1 + z1 * z1);
    unsigned long long* dst = &g_bt[arr][b][j][0];
    dst[0] = X; dst[1] = Y; dst[2] = Z; dst[3] = W;
}

// k2: min-distance. Each block: 256 A points (TA=4 per lane) x one 1024-pt B chunk.
__global__ __launch_bounds__(BDIM) void min_dist_kernel(
    const float* __restrict__ xyz1,
    const float* __restrict__ xyz2)
{
    __shared__ __align__(16) unsigned long long sB[TILE_PAIRS * 4];  // 8KB

    const int bx = blockIdx.x;
    const int aChunk = bx & (NACHUNK - 1);
    const int bChunk = (bx >> 5) & (NBCHUNK - 1);
    const int b      = (bx >> 8) & (NB - 1);
    const int dir    = bx >> 10;

    const float* Aall = (dir == 0) ? xyz1 : xyz2;
    // dir0: B = xyz2 (arr 1); dir1: B = xyz1 (arr 0)
    const unsigned long long* bt = &g_bt[dir == 0 ? 1 : 0][b][0][0];

    const int aBase = aChunk * A_PER_BLK;
    const float* Abase = Aall + (size_t)b * NPTS * 3;

    unsigned long long AX[TA], AY[TA], AZ[TA];
    float best0[TA], best1[TA];
    #pragma unroll
    for (int k = 0; k < TA; k++) {
        const int a = aBase + k * BDIM + threadIdx.x;
        float ax = Abase[a * 3 + 0];
        float ay = Abase[a * 3 + 1];
        float az = Abase[a * 3 + 2];
        PACK2(AX[k], ax, ax);
        PACK2(AY[k], ay, ay);
        PACK2(AZ[k], az, az);
        best0[k] = 3.402823e38f;
        best1[k] = 3.402823e38f;
    }

    const unsigned sbase = (unsigned)__cvta_generic_to_shared(sB);

    for (int tile = 0; tile < TILES_PER_CHUNK; tile++) {
        const int pair0 = bChunk * (BCHUNK_PTS / 2) + tile * TILE_PAIRS;
        __syncthreads();
        {
            const ulonglong2* src = (const ulonglong2*)(bt + (size_t)pair0 * 4);
            ulonglong2* dst = (ulonglong2*)sB;
            #pragma unroll
            for (int i = 0; i < (TILE_PAIRS * 4) / 2 / BDIM; i++)
                dst[i * BDIM + threadIdx.x] = src[i * BDIM + threadIdx.x];
        }
        __syncthreads();

        #pragma unroll 4
        for (int j = 0; j < TILE_PAIRS; j++) {
            unsigned long long x01, y01, z01, w01;
            LDS_V2U64(x01, y01, sbase + j * 32);
            LDS_V2U64(z01, w01, sbase + j * 32 + 16);
            #pragma unroll
            for (int k = 0; k < TA; k++) {
                unsigned long long d;
                FMA2(d, x01, AX[k], w01);
                FMA2(d, y01, AY[k], d);
                FMA2(d, z01, AZ[k], d);
                float d0, d1;
                UNPACK2(d0, d1, d);
                best0[k] = fminf(best0[k], d0);
                best1[k] = fminf(best1[k], d1);
            }
        }
    }

    #pragma unroll
    for (int k = 0; k < TA; k++) {
        const int a = aBase + k * BDIM + threadIdx.x;
        atomicMin(&g_slot[dir][b][a], f2key(fminf(best0[k], best1[k])));
    }
}

// k3: per-A finalize (add s1, clamp, weight) + partial fixed-order reduce.
__global__ __launch_bounds__(256) void combine1_kernel(
    const float* __restrict__ xyz1,
    const float* __restrict__ xyz2,
    const float* __restrict__ w1,
    const float* __restrict__ w2)
{
    __shared__ float s[4][8];
    const int g = blockIdx.x * 256 + threadIdx.x;     // 0..16383
    float num[2] = {0.f, 0.f}, den[2] = {0.f, 0.f};

    #pragma unroll
    for (int rep = 0; rep < 2; rep++) {
        const int i = g + rep * 16384;                 // 0..32767 = b*8192+a
        #pragma unroll
        for (int dir = 0; dir < 2; dir++) {
            const float dp = key2f(((const unsigned*)g_slot)[dir * 32768 + i]);
            const float* A = (dir == 0) ? xyz1 : xyz2;
            float x = A[(size_t)i * 3 + 0];
            float y = A[(size_t)i * 3 + 1];
            float z = A[(size_t)i * 3 + 2];
            const float s1 = x * x + y * y + z * z;
            const float d = fmaxf(s1 + dp, 0.0f);
            const float w = ((dir == 0) ? w1 : w2)[i];
            num[dir] = fmaf(d, w, num[dir]);
            den[dir] += w;
        }
    }

    #pragma unroll
    for (int off = 16; off > 0; off >>= 1) {
        num[0] += __shfl_down_sync(0xffffffffu, num[0], off);
        den[0] += __shfl_down_sync(0xffffffffu, den[0], off);
        num[1] += __shfl_down_sync(0xffffffffu, num[1], off);
        den[1] += __shfl_down_sync(0xffffffffu, den[1], off);
    }
    const int wid = threadIdx.x >> 5;
    if ((threadIdx.x & 31) == 0) {
        s[0][wid] = num[0]; s[1][wid] = den[0];
        s[2][wid] = num[1]; s[3][wid] = den[1];
    }
    __syncthreads();
    if (threadIdx.x == 0) {
        float a0 = 0, a1 = 0, a2 = 0, a3 = 0;
        #pragma unroll
        for (int i = 0; i < 8; i++) {
            a0 += s[0][i]; a1 += s[1][i]; a2 += s[2][i]; a3 += s[3][i];
        }
        g_part[blockIdx.x][0] = a0; g_part[blockIdx.x][1] = a1;
        g_part[blockIdx.x][2] = a2; g_part[blockIdx.x][3] = a3;
    }
}

// k4: final combine of 64 partials.
__global__ __launch_bounds__(64) void combine2_kernel(float* __restrict__ out)
{
    __shared__ float s[4][2];
    const int t = threadIdx.x;
    float a0 = g_part[t][0], a1 = g_part[t][1], a2 = g_part[t][2], a3 = g_part[t][3];
    #pragma unroll
    for (int off = 16; off > 0; off >>= 1) {
        a0 += __shfl_down_sync(0xffffffffu, a0, off);
        a1 += __shfl_down_sync(0xffffffffu, a1, off);
        a2 += __shfl_down_sync(0xffffffffu, a2, off);
        a3 += __shfl_down_sync(0xffffffffu, a3, off);
    }
    const int wid = t >> 5;
    if ((t & 31) == 0) {
        s[0][wid] = a0; s[1][wid] = a1; s[2][wid] = a2; s[3][wid] = a3;
    }
    __syncthreads();
    if (t == 0) {
        float N0 = s[0][0] + s[0][1];
        float D0 = s[1][0] + s[1][1];
        float N1 = s[2][0] + s[2][1];
        float D1 = s[3][0] + s[3][1];
        out[0] = 0.5f * (N0 / D0 + N1 / D1);
    }
}

extern "C" void kernel_launch(void* const* d_in, const int* in_sizes, int n_in,
                              void* d_out, int out_size)
{
    const float* xyz1 = (const float*)d_in[0];
    const float* xyz2 = (const float*)d_in[1];
    const float* w1   = (const float*)d_in[2];
    const float* w2   = (const float*)d_in[3];
    float* out        = (float*)d_out;

    transform_kernel<<<128, 256>>>(xyz1, xyz2);
    min_dist_kernel<<<NBLOCKS, BDIM>>>(xyz1, xyz2);
    combine1_kernel<<<64, 256>>>(xyz1, xyz2, w1, w2);
    combine2_kernel<<<1, 64>>>(out);
}